// round 11
// baseline (speedup 1.0000x reference)
#include <cuda_runtime.h>

#define NB     4096
#define MAXKV  64
#define CTA    64               // 2 warps/CTA, warp per logical block
#define GRIDAB (NB / 2)         // 2048 CTAs -> 4096 warps

// Packed per-block scratch. Fully rewritten each launch (g_done reset by last user).
__device__ float2 g_pk[NB];    // (Σ p·keep, Σ keep)   <- gathered by neighbors
__device__ float4 g_own[NB];   // (Σ p·unc, Σ p²·unc, Σ unc, 0)
__device__ float4 g_fin[NB];   // (bce, sup) written by A; (gl, val) written by B
__device__ int    g_done;      // last-CTA-done counter (zero-init, reset after use)

__device__ __forceinline__ float warp_sum(float v) {
#pragma unroll
    for (int o = 16; o > 0; o >>= 1) v += __shfl_down_sync(0xffffffffu, v, o);
    return v;
}

// ---------------- Kernel A: per-node math -> packed per-block scalars ----------------
__global__ void __launch_bounds__(CTA) kernA(const float4* __restrict__ x4,
                                             const float4* __restrict__ t4,
                                             const uint4*  __restrict__ s4,
                                             const uint4*  __restrict__ i4) {
    cudaTriggerProgrammaticLaunchCompletion();

    const int lane = threadIdx.x & 31;
    const int b    = blockIdx.x * 2 + (threadIdx.x >> 5);   // logical block
    const int vidx = b * 32 + lane;

    // Front-batched independent LDG.128 x4
    const float4 xv = x4[vidx];
    const float4 tv = t4[vidx];
    const uint4  sv = s4[vidx];
    const uint4  iv = i4[vidx];

    float bce_s = 0.f, pk_s = 0.f, p1 = 0.f, p2 = 0.f;
    unsigned cnt_s = 0, cnt_k = 0, cnt_q = 0;   // warp-wide counts via ballot/popc
    {
        const float xs[4] = {xv.x, xv.y, xv.z, xv.w};
        const float ts[4] = {tv.x, tv.y, tv.z, tv.w};
        const unsigned int ss[4] = {sv.x, sv.y, sv.z, sv.w};
        const unsigned int is[4] = {iv.x, iv.y, iv.z, iv.w};
#pragma unroll
        for (int k = 0; k < 4; k++) {
            const float x = xs[k];
            const float e   = __expf(-fabsf(x));            // one exp for softplus+sigmoid
            const float inv = 1.0f / (1.0f + e);
            const float p   = (x >= 0.0f) ? inv : e * inv;
            const float sp  = fmaxf(x, 0.0f) + __logf(1.0f + e);
            const bool s    = ss[k] != 0u;
            const bool keep = is[k] == 0u;
            const bool unc  = keep && !s;
            cnt_s += __popc(__ballot_sync(0xffffffffu, s));
            cnt_k += __popc(__ballot_sync(0xffffffffu, keep));
            cnt_q += __popc(__ballot_sync(0xffffffffu, unc));
            if (s)    { bce_s += sp - ts[k] * x; }
            if (keep) { pk_s  += p; }
            if (unc)  { p1 += p; p2 += p * p; }
        }
    }
    bce_s = warp_sum(bce_s);
    pk_s  = warp_sum(pk_s);
    p1    = warp_sum(p1);
    p2    = warp_sum(p2);
    if (lane == 0) {
        g_pk[b]  = make_float2(pk_s, (float)cnt_k);
        g_own[b] = make_float4(p1, p2, (float)cnt_q, 0.0f);
        *(float2*)&g_fin[b] = make_float2(bce_s, (float)cnt_s);   // .xy
    }
}

// ---------------- Kernel B: PDL-overlapped gather + closed-form loss + last-CTA reduce ----------------
__global__ void __launch_bounds__(CTA) kernB(const uint2* __restrict__ kvi2,
                                             const int*   __restrict__ kvn,
                                             float* __restrict__ out) {
    const int tid  = threadIdx.x;
    const int lane = tid & 31;
    const int wid  = tid >> 5;
    const int b    = blockIdx.x * 2 + wid;

    // External-input loads issued before the dependency sync (overlap with kernA).
    const uint2 jj = kvi2[b * 32 + lane];
    const int   nb = kvn[b];

    cudaGridDependencySynchronize();   // kernA's g_pk/g_own/g_fin now visible

    float ns = 0.0f, nc = 0.0f;
    if (2 * lane < nb)     { const float2 v = g_pk[jj.x]; ns += v.x; nc += v.y; }
    if (2 * lane + 1 < nb) { const float2 v = g_pk[jj.y]; ns += v.x; nc += v.y; }
    ns = warp_sum(ns);
    nc = warp_sum(nc);
    if (lane == 0) {
        const float  m  = ns / fmaxf(nc, 1.0f);
        const float4 ow = g_own[b];                              // (p1, p2, q, 0)
        const float  sq = ow.y - 2.0f * m * ow.x + ow.z * m * m; // Σ_unc (p-m)²
        const bool valid = (ow.z > 0.0f) && (nc > 0.0f);
        *(float2*)(&g_fin[b].z) = make_float2(valid ? (sq / fmaxf(ow.z, 1.0f)) : 0.0f,
                                              valid ? 1.0f : 0.0f);   // .zw
    }

    // ---- last-CTA-done final reduction ----
    __syncthreads();
    __shared__ int s_last;
    if (tid == 0) {
        __threadfence();                    // release this CTA's g_fin writes
        s_last = (atomicAdd(&g_done, 1) == GRIDAB - 1) ? 1 : 0;
    }
    __syncthreads();
    if (!s_last) return;

    __threadfence();                        // acquire all CTAs' g_fin writes
    float a = 0.f, bb = 0.f, c = 0.f, d = 0.f;
#pragma unroll 4
    for (int i = tid; i < NB; i += CTA) {
        const float4 r = g_fin[i];          // one LDG.128 per entry
        a += r.x; bb += r.y; c += r.z; d += r.w;
    }
    a = warp_sum(a); bb = warp_sum(bb); c = warp_sum(c); d = warp_sum(d);
    __shared__ float4 sh[2];
    if (lane == 0) sh[wid] = make_float4(a, bb, c, d);
    __syncthreads();
    if (tid == 0) {
        const float A = sh[0].x + sh[1].x;
        const float B = sh[0].y + sh[1].y;
        const float C = sh[0].z + sh[1].z;
        const float D = sh[0].w + sh[1].w;
        const float loss_sup   = (B > 0.0f) ? (A / fmaxf(B, 1.0f)) : 0.0f;
        const float loss_graph = C / fmaxf(D, 1.0f);
        out[0] = loss_sup + 0.3f * loss_graph;
        g_done = 0;   // reset for next graph replay
    }
}

extern "C" void kernel_launch(void* const* d_in, const int* in_sizes, int n_in,
                              void* d_out, int out_size) {
    const float4* x4   = (const float4*)d_in[0];  // logits   [524288] f32
    const float4* t4   = (const float4*)d_in[1];  // targets  [524288] f32
    const uint4*  s4   = (const uint4*)d_in[2];   // sup_mask  (4-byte bool)
    const uint4*  i4   = (const uint4*)d_in[3];   // ignore_mask
    const uint2*  kvi2 = (const uint2*)d_in[4];   // kv_indices [4096*64] as uint2
    const int*    kvn  = (const int*)d_in[5];     // kv_num_blocks [4096]
    (void)in_sizes; (void)n_in; (void)out_size;

    kernA<<<GRIDAB, CTA>>>(x4, t4, s4, i4);

    cudaLaunchConfig_t cfg = {};
    cfg.gridDim  = dim3(GRIDAB, 1, 1);
    cfg.blockDim = dim3(CTA, 1, 1);
    cfg.dynamicSmemBytes = 0;
    cudaLaunchAttribute attr[1];
    attr[0].id = cudaLaunchAttributeProgrammaticStreamSerialization;
    attr[0].val.programmaticStreamSerializationAllowed = 1;
    cfg.attrs = attr;
    cfg.numAttrs = 1;
    cudaLaunchKernelEx(&cfg, kernB, kvi2, kvn, (float*)d_out);
}

// round 12
// speedup vs baseline: 1.1733x; 1.1733x over previous
#include <cuda_runtime.h>

#define NB     4096
#define MAXKV  64
#define CTA    128              // 4 warps/CTA, warp per logical block (R7 proven shape)
#define GRIDAB (NB / 4)         // 1024 CTAs -> 4096 warps

// Packed per-block scratch. Fully rewritten each launch (g_done reset by last user).
__device__ float2 g_pk[NB];    // (Σ p·keep, Σ keep)   <- gathered by neighbors
__device__ float4 g_own[NB];   // (Σ p·unc, Σ p²·unc, Σ unc, 0)
__device__ float4 g_fin[NB];   // (bce, sup) written by A; (gl, val) written by B
__device__ int    g_done;      // last-CTA-done counter (zero-init, reset after use)

__device__ __forceinline__ float warp_sum(float v) {
#pragma unroll
    for (int o = 16; o > 0; o >>= 1) v += __shfl_down_sync(0xffffffffu, v, o);
    return v;
}

// ---------------- Kernel A: per-node math -> packed per-block scalars ----------------
__global__ void __launch_bounds__(CTA) kernA(const float4* __restrict__ x4,
                                             const float4* __restrict__ t4,
                                             const uint4*  __restrict__ s4,
                                             const uint4*  __restrict__ i4) {
    cudaTriggerProgrammaticLaunchCompletion();

    const int lane = threadIdx.x & 31;
    const int b    = blockIdx.x * 4 + (threadIdx.x >> 5);   // logical block
    const int vidx = b * 32 + lane;

    // Front-batched independent LDG.128 x4
    const float4 xv = x4[vidx];
    const float4 tv = t4[vidx];
    const uint4  sv = s4[vidx];
    const uint4  iv = i4[vidx];

    float bce_s = 0.f, pk_s = 0.f, p1 = 0.f, p2 = 0.f;
    unsigned cnt_s = 0, cnt_k = 0, cnt_q = 0;   // warp counts via ballot/popc (no shuffle trees)
    {
        const float xs[4] = {xv.x, xv.y, xv.z, xv.w};
        const float ts[4] = {tv.x, tv.y, tv.z, tv.w};
        const unsigned int ss[4] = {sv.x, sv.y, sv.z, sv.w};
        const unsigned int is[4] = {iv.x, iv.y, iv.z, iv.w};
#pragma unroll
        for (int k = 0; k < 4; k++) {
            const float x = xs[k];
            const float e   = __expf(-fabsf(x));            // one exp for softplus+sigmoid
            const float inv = 1.0f / (1.0f + e);
            const float p   = (x >= 0.0f) ? inv : e * inv;
            const float sp  = fmaxf(x, 0.0f) + __logf(1.0f + e);
            const bool s    = ss[k] != 0u;
            const bool keep = is[k] == 0u;
            const bool unc  = keep && !s;
            cnt_s += __popc(__ballot_sync(0xffffffffu, s));
            cnt_k += __popc(__ballot_sync(0xffffffffu, keep));
            cnt_q += __popc(__ballot_sync(0xffffffffu, unc));
            if (s)    { bce_s += sp - ts[k] * x; }
            if (keep) { pk_s  += p; }
            if (unc)  { p1 += p; p2 += p * p; }
        }
    }
    bce_s = warp_sum(bce_s);
    pk_s  = warp_sum(pk_s);
    p1    = warp_sum(p1);
    p2    = warp_sum(p2);
    if (lane == 0) {
        g_pk[b]  = make_float2(pk_s, (float)cnt_k);
        g_own[b] = make_float4(p1, p2, (float)cnt_q, 0.0f);
        *(float2*)&g_fin[b] = make_float2(bce_s, (float)cnt_s);   // .xy
    }
}

// ---------------- Kernel B: PDL-overlapped gather + closed-form loss + last-CTA reduce ----------------
__global__ void __launch_bounds__(CTA) kernB(const uint2* __restrict__ kvi2,
                                             const int*   __restrict__ kvn,
                                             float* __restrict__ out) {
    const int tid  = threadIdx.x;
    const int lane = tid & 31;
    const int wid  = tid >> 5;
    const int b    = blockIdx.x * 4 + wid;

    // External-input loads issued before the dependency sync (overlap with kernA).
    const uint2 jj = kvi2[b * 32 + lane];
    const int   nb = kvn[b];

    cudaGridDependencySynchronize();   // kernA's g_pk/g_own/g_fin now visible

    // Hoisted: lane 0's g_own load overlaps the gather + reduction below.
    float4 ow = make_float4(0.f, 0.f, 0.f, 0.f);
    if (lane == 0) ow = g_own[b];

    float ns = 0.0f, nc = 0.0f;
    if (2 * lane < nb)     { const float2 v = g_pk[jj.x]; ns += v.x; nc += v.y; }
    if (2 * lane + 1 < nb) { const float2 v = g_pk[jj.y]; ns += v.x; nc += v.y; }
    ns = warp_sum(ns);
    nc = warp_sum(nc);
    if (lane == 0) {
        const float m  = ns / fmaxf(nc, 1.0f);
        const float sq = ow.y - 2.0f * m * ow.x + ow.z * m * m;  // Σ_unc (p-m)²
        const bool valid = (ow.z > 0.0f) && (nc > 0.0f);
        *(float2*)(&g_fin[b].z) = make_float2(valid ? (sq / fmaxf(ow.z, 1.0f)) : 0.0f,
                                              valid ? 1.0f : 0.0f);   // .zw
    }

    // ---- last-CTA-done final reduction ----
    __syncthreads();
    __shared__ int s_last;
    if (tid == 0) {
        __threadfence();                    // release this CTA's g_fin writes
        s_last = (atomicAdd(&g_done, 1) == GRIDAB - 1) ? 1 : 0;
    }
    __syncthreads();
    if (!s_last) return;

    __threadfence();                        // acquire all CTAs' g_fin writes
    float a = 0.f, bb = 0.f, c = 0.f, d = 0.f;
#pragma unroll 4
    for (int i = tid; i < NB; i += CTA) {
        const float4 r = g_fin[i];          // one LDG.128 per entry
        a += r.x; bb += r.y; c += r.z; d += r.w;
    }
    a = warp_sum(a); bb = warp_sum(bb); c = warp_sum(c); d = warp_sum(d);
    __shared__ float sh[4][4];
    if (lane == 0) { sh[0][wid] = a; sh[1][wid] = bb; sh[2][wid] = c; sh[3][wid] = d; }
    __syncthreads();
    if (tid == 0) {
        float A = 0.f, B = 0.f, C = 0.f, D = 0.f;
#pragma unroll
        for (int i = 0; i < 4; i++) { A += sh[0][i]; B += sh[1][i]; C += sh[2][i]; D += sh[3][i]; }
        const float loss_sup   = (B > 0.0f) ? (A / fmaxf(B, 1.0f)) : 0.0f;
        const float loss_graph = C / fmaxf(D, 1.0f);
        out[0] = loss_sup + 0.3f * loss_graph;
        g_done = 0;   // reset for next graph replay
    }
}

extern "C" void kernel_launch(void* const* d_in, const int* in_sizes, int n_in,
                              void* d_out, int out_size) {
    const float4* x4   = (const float4*)d_in[0];  // logits   [524288] f32
    const float4* t4   = (const float4*)d_in[1];  // targets  [524288] f32
    const uint4*  s4   = (const uint4*)d_in[2];   // sup_mask  (4-byte bool)
    const uint4*  i4   = (const uint4*)d_in[3];   // ignore_mask
    const uint2*  kvi2 = (const uint2*)d_in[4];   // kv_indices [4096*64] as uint2
    const int*    kvn  = (const int*)d_in[5];     // kv_num_blocks [4096]
    (void)in_sizes; (void)n_in; (void)out_size;

    kernA<<<GRIDAB, CTA>>>(x4, t4, s4, i4);

    cudaLaunchConfig_t cfg = {};
    cfg.gridDim  = dim3(GRIDAB, 1, 1);
    cfg.blockDim = dim3(CTA, 1, 1);
    cfg.dynamicSmemBytes = 0;
    cudaLaunchAttribute attr[1];
    attr[0].id = cudaLaunchAttributeProgrammaticStreamSerialization;
    attr[0].val.programmaticStreamSerializationAllowed = 1;
    cfg.attrs = attr;
    cfg.numAttrs = 1;
    cudaLaunchKernelEx(&cfg, kernB, kvi2, kvn, (float*)d_out);
}

// round 13
// speedup vs baseline: 1.2973x; 1.1057x over previous
#include <cuda_runtime.h>

#define NB     4096
#define MAXKV  64
#define CTA    128              // 4 warps/CTA, warp per logical block
#define GRIDAB (NB / 4)         // 1024 CTAs -> 4096 warps

// Packed scratch. Fully rewritten each launch (g_done reset by last user).
__device__ float2 g_pk[NB];      // (Σ p·keep, Σ keep)  <- gathered by neighbors
__device__ float4 g_own[NB];     // (Σ p·unc, Σ p²·unc, Σ unc, 0)
__device__ float2 g_bsc[GRIDAB]; // per-CTA (Σ bce·sup, Σ sup)   written by kernA
__device__ float2 g_gvc[GRIDAB]; // per-CTA (Σ gl, Σ valid)      written by kernB
__device__ int    g_done;        // last-CTA-done counter

__device__ __forceinline__ float warp_sum(float v) {
#pragma unroll
    for (int o = 16; o > 0; o >>= 1) v += __shfl_down_sync(0xffffffffu, v, o);
    return v;
}

// ---------------- Kernel A: per-node math -> packed per-block + per-CTA scalars ----------------
__global__ void __launch_bounds__(CTA) kernA(const float4* __restrict__ x4,
                                             const float4* __restrict__ t4,
                                             const uint4*  __restrict__ s4,
                                             const uint4*  __restrict__ i4) {
    cudaTriggerProgrammaticLaunchCompletion();

    const int lane = threadIdx.x & 31;
    const int wid  = threadIdx.x >> 5;
    const int b    = blockIdx.x * 4 + wid;   // logical block
    const int vidx = b * 32 + lane;

    // Front-batched independent LDG.128 x4
    const float4 xv = x4[vidx];
    const float4 tv = t4[vidx];
    const uint4  sv = s4[vidx];
    const uint4  iv = i4[vidx];

    float bce_s = 0.f, pk_s = 0.f, p1 = 0.f, p2 = 0.f;
    unsigned cnt_s = 0, cnt_k = 0, cnt_q = 0;   // counts via ballot/popc
    {
        const float xs[4] = {xv.x, xv.y, xv.z, xv.w};
        const float ts[4] = {tv.x, tv.y, tv.z, tv.w};
        const unsigned int ss[4] = {sv.x, sv.y, sv.z, sv.w};
        const unsigned int is[4] = {iv.x, iv.y, iv.z, iv.w};
#pragma unroll
        for (int k = 0; k < 4; k++) {
            const float x = xs[k];
            const float e   = __expf(-fabsf(x));            // one exp for softplus+sigmoid
            const float inv = 1.0f / (1.0f + e);
            const float p   = (x >= 0.0f) ? inv : e * inv;
            const float sp  = fmaxf(x, 0.0f) + __logf(1.0f + e);
            const bool s    = ss[k] != 0u;
            const bool keep = is[k] == 0u;
            const bool unc  = keep && !s;
            cnt_s += __popc(__ballot_sync(0xffffffffu, s));
            cnt_k += __popc(__ballot_sync(0xffffffffu, keep));
            cnt_q += __popc(__ballot_sync(0xffffffffu, unc));
            if (s)    { bce_s += sp - ts[k] * x; }
            if (keep) { pk_s  += p; }
            if (unc)  { p1 += p; p2 += p * p; }
        }
    }
    bce_s = warp_sum(bce_s);
    pk_s  = warp_sum(pk_s);
    p1    = warp_sum(p1);
    p2    = warp_sum(p2);

    __shared__ float2 shb[4];
    if (lane == 0) {
        g_pk[b]  = make_float2(pk_s, (float)cnt_k);
        g_own[b] = make_float4(p1, p2, (float)cnt_q, 0.0f);
        shb[wid] = make_float2(bce_s, (float)cnt_s);
    }
    __syncthreads();
    if (threadIdx.x == 0) {   // per-CTA (bce, sup) partial
        g_bsc[blockIdx.x] = make_float2(shb[0].x + shb[1].x + shb[2].x + shb[3].x,
                                        shb[0].y + shb[1].y + shb[2].y + shb[3].y);
    }
}

// ---------------- Kernel B: PDL gather + closed-form loss + per-CTA partial + last-CTA reduce ----------------
__global__ void __launch_bounds__(CTA) kernB(const uint2* __restrict__ kvi2,
                                             const int*   __restrict__ kvn,
                                             float* __restrict__ out) {
    const int tid  = threadIdx.x;
    const int lane = tid & 31;
    const int wid  = tid >> 5;
    const int b    = blockIdx.x * 4 + wid;

    // External-input loads before the dependency sync (overlap with kernA).
    const uint2 jj = kvi2[b * 32 + lane];
    const int   nb = kvn[b];

    cudaGridDependencySynchronize();   // kernA's outputs now visible

    // Hoisted: lane 0's g_own load overlaps the gather + reduction below.
    float4 ow = make_float4(0.f, 0.f, 0.f, 0.f);
    if (lane == 0) ow = g_own[b];

    float ns = 0.0f, nc = 0.0f;
    if (2 * lane < nb)     { const float2 v = g_pk[jj.x]; ns += v.x; nc += v.y; }
    if (2 * lane + 1 < nb) { const float2 v = g_pk[jj.y]; ns += v.x; nc += v.y; }
    ns = warp_sum(ns);
    nc = warp_sum(nc);

    __shared__ float2 shg[4];
    if (lane == 0) {
        const float m  = ns / fmaxf(nc, 1.0f);
        const float sq = ow.y - 2.0f * m * ow.x + ow.z * m * m;  // Σ_unc (p-m)²
        const bool valid = (ow.z > 0.0f) && (nc > 0.0f);
        shg[wid] = make_float2(valid ? (sq / fmaxf(ow.z, 1.0f)) : 0.0f,
                               valid ? 1.0f : 0.0f);
    }
    __syncthreads();
    __shared__ int s_last;
    if (tid == 0) {
        g_gvc[blockIdx.x] = make_float2(shg[0].x + shg[1].x + shg[2].x + shg[3].x,
                                        shg[0].y + shg[1].y + shg[2].y + shg[3].y);
        __threadfence();                    // release this CTA's partial
        s_last = (atomicAdd(&g_done, 1) == GRIDAB - 1) ? 1 : 0;
    }
    __syncthreads();
    if (!s_last) return;

    // ---- Last CTA: reduce 2x1024 float2 (16 KB, high-MLP) ----
    __threadfence();                        // acquire all CTAs' partials
    float a = 0.f, bb = 0.f, c = 0.f, d = 0.f;
#pragma unroll
    for (int i = 0; i < GRIDAB / CTA; i++) {          // 8 iterations, MLP-batched
        const float2 bs = g_bsc[i * CTA + tid];
        const float2 gv = g_gvc[i * CTA + tid];
        a += bs.x; bb += bs.y; c += gv.x; d += gv.y;
    }
    a = warp_sum(a); bb = warp_sum(bb); c = warp_sum(c); d = warp_sum(d);
    __shared__ float sh[4][4];
    if (lane == 0) { sh[0][wid] = a; sh[1][wid] = bb; sh[2][wid] = c; sh[3][wid] = d; }
    __syncthreads();
    if (tid == 0) {
        float A = 0.f, B = 0.f, C = 0.f, D = 0.f;
#pragma unroll
        for (int i = 0; i < 4; i++) { A += sh[0][i]; B += sh[1][i]; C += sh[2][i]; D += sh[3][i]; }
        const float loss_sup   = (B > 0.0f) ? (A / fmaxf(B, 1.0f)) : 0.0f;
        const float loss_graph = C / fmaxf(D, 1.0f);
        out[0] = loss_sup + 0.3f * loss_graph;
        g_done = 0;   // reset for next graph replay
    }
}

extern "C" void kernel_launch(void* const* d_in, const int* in_sizes, int n_in,
                              void* d_out, int out_size) {
    const float4* x4   = (const float4*)d_in[0];  // logits   [524288] f32
    const float4* t4   = (const float4*)d_in[1];  // targets  [524288] f32
    const uint4*  s4   = (const uint4*)d_in[2];   // sup_mask  (4-byte bool)
    const uint4*  i4   = (const uint4*)d_in[3];   // ignore_mask
    const uint2*  kvi2 = (const uint2*)d_in[4];   // kv_indices [4096*64] as uint2
    const int*    kvn  = (const int*)d_in[5];     // kv_num_blocks [4096]
    (void)in_sizes; (void)n_in; (void)out_size;

    kernA<<<GRIDAB, CTA>>>(x4, t4, s4, i4);

    cudaLaunchConfig_t cfg = {};
    cfg.gridDim  = dim3(GRIDAB, 1, 1);
    cfg.blockDim = dim3(CTA, 1, 1);
    cfg.dynamicSmemBytes = 0;
    cudaLaunchAttribute attr[1];
    attr[0].id = cudaLaunchAttributeProgrammaticStreamSerialization;
    attr[0].val.programmaticStreamSerializationAllowed = 1;
    cfg.attrs = attr;
    cfg.numAttrs = 1;
    cudaLaunchKernelEx(&cfg, kernB, kvi2, kvn, (float*)d_out);
}

// round 14
// speedup vs baseline: 1.4958x; 1.1530x over previous
#include <cuda_runtime.h>

#define NB     4096
#define MAXKV  64
#define CTA    128              // 4 warps/CTA, warp per logical block
#define GRIDAB (NB / 4)         // 1024 CTAs -> 4096 warps

// Packed scratch. Fully rewritten each launch (g_done reset by last user).
__device__ float2 g_pk[NB];      // (Σ p·keep, Σ keep)  <- gathered by neighbors
__device__ float4 g_own[NB];     // (Σ p·unc, Σ p²·unc, Σ unc, 0)
__device__ float2 g_bsc[GRIDAB]; // per-CTA (Σ bce·sup, Σ sup)   written by kernA
__device__ float2 g_gvc[GRIDAB]; // per-CTA (Σ gl, Σ valid)      written by kernB
__device__ int    g_done;        // last-CTA-done counter

__device__ __forceinline__ float warp_sum(float v) {
#pragma unroll
    for (int o = 16; o > 0; o >>= 1) v += __shfl_down_sync(0xffffffffu, v, o);
    return v;
}

// HW tanh (sm_75+): 1 MUFU op, rel err ~2^-11.
__device__ __forceinline__ float tanh_fast(float x) {
    float r;
    asm("tanh.approx.f32 %0, %1;" : "=f"(r) : "f"(x));
    return r;
}

// ---------------- Kernel A: per-node math -> packed per-block + per-CTA scalars ----------------
__global__ void __launch_bounds__(CTA) kernA(const float4* __restrict__ x4,
                                             const float4* __restrict__ t4,
                                             const uint4*  __restrict__ s4,
                                             const uint4*  __restrict__ i4) {
    cudaTriggerProgrammaticLaunchCompletion();

    const int lane = threadIdx.x & 31;
    const int wid  = threadIdx.x >> 5;
    const int b    = blockIdx.x * 4 + wid;   // logical block
    const int vidx = b * 32 + lane;

    // Front-batched independent LDG.128 x4
    const float4 xv = x4[vidx];
    const float4 tv = t4[vidx];
    const uint4  sv = s4[vidx];
    const uint4  iv = i4[vidx];

    float bce_s = 0.f, pk_s = 0.f, p1 = 0.f, p2 = 0.f;
    unsigned cnt_s = 0, cnt_k = 0, cnt_q = 0;   // counts via ballot/popc
    {
        const float xs[4] = {xv.x, xv.y, xv.z, xv.w};
        const float ts[4] = {tv.x, tv.y, tv.z, tv.w};
        const unsigned int ss[4] = {sv.x, sv.y, sv.z, sv.w};
        const unsigned int is[4] = {iv.x, iv.y, iv.z, iv.w};
#pragma unroll
        for (int k = 0; k < 4; k++) {
            const float x  = xs[k];
            const float ax = fabsf(x);
            // sigmoid(|x|) = 0.5 + 0.5*tanh(|x|/2)   [1 MUFU]
            const float pp = fmaf(0.5f, tanh_fast(0.5f * ax), 0.5f);
            // softplus(x) = max(x,0) - log(sigmoid(|x|))   [1 MUFU]
            const float sp = fmaxf(x, 0.0f) - __logf(pp);
            // sigmoid(x)
            const float p  = (x >= 0.0f) ? pp : (1.0f - pp);
            const bool s    = ss[k] != 0u;
            const bool keep = is[k] == 0u;
            const bool unc  = keep && !s;
            cnt_s += __popc(__ballot_sync(0xffffffffu, s));
            cnt_k += __popc(__ballot_sync(0xffffffffu, keep));
            cnt_q += __popc(__ballot_sync(0xffffffffu, unc));
            if (s)    { bce_s += sp - ts[k] * x; }
            if (keep) { pk_s  += p; }
            if (unc)  { p1 += p; p2 += p * p; }
        }
    }
    bce_s = warp_sum(bce_s);
    pk_s  = warp_sum(pk_s);
    p1    = warp_sum(p1);
    p2    = warp_sum(p2);

    __shared__ float2 shb[4];
    if (lane == 0) {
        g_pk[b]  = make_float2(pk_s, (float)cnt_k);
        g_own[b] = make_float4(p1, p2, (float)cnt_q, 0.0f);
        shb[wid] = make_float2(bce_s, (float)cnt_s);
    }
    __syncthreads();
    if (threadIdx.x == 0) {   // per-CTA (bce, sup) partial
        g_bsc[blockIdx.x] = make_float2(shb[0].x + shb[1].x + shb[2].x + shb[3].x,
                                        shb[0].y + shb[1].y + shb[2].y + shb[3].y);
    }
}

// ---------------- Kernel B: PDL gather + closed-form loss + per-CTA partial + last-CTA reduce ----------------
__global__ void __launch_bounds__(CTA) kernB(const uint2* __restrict__ kvi2,
                                             const int*   __restrict__ kvn,
                                             float* __restrict__ out) {
    const int tid  = threadIdx.x;
    const int lane = tid & 31;
    const int wid  = tid >> 5;
    const int b    = blockIdx.x * 4 + wid;

    // External-input loads before the dependency sync (overlap with kernA).
    const uint2 jj = kvi2[b * 32 + lane];
    const int   nb = kvn[b];

    cudaGridDependencySynchronize();   // kernA's outputs now visible

    // Hoisted: lane 0's g_own load overlaps the gather + reduction below.
    float4 ow = make_float4(0.f, 0.f, 0.f, 0.f);
    if (lane == 0) ow = g_own[b];

    float ns = 0.0f, nc = 0.0f;
    if (2 * lane < nb)     { const float2 v = g_pk[jj.x]; ns += v.x; nc += v.y; }
    if (2 * lane + 1 < nb) { const float2 v = g_pk[jj.y]; ns += v.x; nc += v.y; }
    ns = warp_sum(ns);
    nc = warp_sum(nc);

    __shared__ float2 shg[4];
    if (lane == 0) {
        const float m  = ns / fmaxf(nc, 1.0f);
        const float sq = ow.y - 2.0f * m * ow.x + ow.z * m * m;  // Σ_unc (p-m)²
        const bool valid = (ow.z > 0.0f) && (nc > 0.0f);
        shg[wid] = make_float2(valid ? (sq / fmaxf(ow.z, 1.0f)) : 0.0f,
                               valid ? 1.0f : 0.0f);
    }
    __syncthreads();
    __shared__ int s_last;
    if (tid == 0) {
        g_gvc[blockIdx.x] = make_float2(shg[0].x + shg[1].x + shg[2].x + shg[3].x,
                                        shg[0].y + shg[1].y + shg[2].y + shg[3].y);
        __threadfence();                    // release this CTA's partial
        s_last = (atomicAdd(&g_done, 1) == GRIDAB - 1) ? 1 : 0;
    }
    __syncthreads();
    if (!s_last) return;

    // ---- Last CTA: reduce 2x1024 float2 (16 KB, high-MLP) ----
    __threadfence();                        // acquire all CTAs' partials
    float a = 0.f, bb = 0.f, c = 0.f, d = 0.f;
#pragma unroll
    for (int i = 0; i < GRIDAB / CTA; i++) {          // 8 iterations, MLP-batched
        const float2 bs = g_bsc[i * CTA + tid];
        const float2 gv = g_gvc[i * CTA + tid];
        a += bs.x; bb += bs.y; c += gv.x; d += gv.y;
    }
    a = warp_sum(a); bb = warp_sum(bb); c = warp_sum(c); d = warp_sum(d);
    __shared__ float sh[4][4];
    if (lane == 0) { sh[0][wid] = a; sh[1][wid] = bb; sh[2][wid] = c; sh[3][wid] = d; }
    __syncthreads();
    if (tid == 0) {
        float A = 0.f, B = 0.f, C = 0.f, D = 0.f;
#pragma unroll
        for (int i = 0; i < 4; i++) { A += sh[0][i]; B += sh[1][i]; C += sh[2][i]; D += sh[3][i]; }
        const float loss_sup   = (B > 0.0f) ? (A / fmaxf(B, 1.0f)) : 0.0f;
        const float loss_graph = C / fmaxf(D, 1.0f);
        out[0] = loss_sup + 0.3f * loss_graph;
        g_done = 0;   // reset for next graph replay
    }
}

extern "C" void kernel_launch(void* const* d_in, const int* in_sizes, int n_in,
                              void* d_out, int out_size) {
    const float4* x4   = (const float4*)d_in[0];  // logits   [524288] f32
    const float4* t4   = (const float4*)d_in[1];  // targets  [524288] f32
    const uint4*  s4   = (const uint4*)d_in[2];   // sup_mask  (4-byte bool)
    const uint4*  i4   = (const uint4*)d_in[3];   // ignore_mask
    const uint2*  kvi2 = (const uint2*)d_in[4];   // kv_indices [4096*64] as uint2
    const int*    kvn  = (const int*)d_in[5];     // kv_num_blocks [4096]
    (void)in_sizes; (void)n_in; (void)out_size;

    kernA<<<GRIDAB, CTA>>>(x4, t4, s4, i4);

    cudaLaunchConfig_t cfg = {};
    cfg.gridDim  = dim3(GRIDAB, 1, 1);
    cfg.blockDim = dim3(CTA, 1, 1);
    cfg.dynamicSmemBytes = 0;
    cudaLaunchAttribute attr[1];
    attr[0].id = cudaLaunchAttributeProgrammaticStreamSerialization;
    attr[0].val.programmaticStreamSerializationAllowed = 1;
    cfg.attrs = attr;
    cfg.numAttrs = 1;
    cudaLaunchKernelEx(&cfg, kernB, kvi2, kvn, (float*)d_out);
}